// round 2
// baseline (speedup 1.0000x reference)
#include <cuda_runtime.h>

// SimpleGate: h = relu(x@w1+b1); logits = h@w2+b2; top-2 softmax scattered dense.
// x [16384,4096] f32, w1 [4096,256], b1 [256], w2 [256,64], b2 [64] -> out [16384,64] f32.
//
// R1 strategy: fp32-exact everywhere (top-2 *selection* is the accuracy-critical
// part; bf16/tf32 single-pass provably fails the 1e-3 rel-err gate due to index
// flips). SIMT SGEMM baseline; tensor-core tf32-split planned for next rounds.

#define M_TOK 16384
#define K_IN  4096
#define N_HID 256
#define N_EXP 64

// intermediate h = relu(x@w1+b1), 16 MB scratch (static: no allocations allowed)
__device__ float g_h[(size_t)M_TOK * N_HID];

// ---------------------------------------------------------------------------
// Kernel 1: SGEMM  h = relu(x @ w1 + b1)
// Tile: BM=128, BN=128, BK=32; 256 threads; 8x8 accum per thread;
// global->register prefetch of next K-tile overlapped with compute.
// ---------------------------------------------------------------------------
#define BM 128
#define BN 128
#define BK 32

__global__ __launch_bounds__(256, 2) void gemm1_relu(
    const float* __restrict__ A,     // x [M,K]
    const float* __restrict__ W,     // w1 [K,N]
    const float* __restrict__ bias)  // b1 [N]
{
    __shared__ float As[BM][BK + 4];   // +4 pad: conflict-free f4 stores
    __shared__ float Bs[BK][BN];

    const int tid = threadIdx.x;
    const int tx  = tid & 15;          // output col group (8 cols)
    const int ty  = tid >> 4;          // output row group (8 rows)
    const int rowA0 = blockIdx.y * BM;
    const int colB0 = blockIdx.x * BN;

    // A tile loaders: 128x32 floats = 1024 f4; 4 f4/thread
    const int aRow = tid >> 3;           // 0..31
    const int aCol = (tid & 7) * 4;      // 0..28
    // B tile loaders: 32x128 floats = 1024 f4; 4 f4/thread
    const int bRow = tid >> 5;           // 0..7
    const int bCol = (tid & 31) * 4;     // 0..124

    const float* Abase = A + (size_t)rowA0 * K_IN;

    float acc[8][8];
    #pragma unroll
    for (int i = 0; i < 8; i++)
        #pragma unroll
        for (int j = 0; j < 8; j++) acc[i][j] = 0.f;

    float4 pa[4], pb[4];

    // tile 0 -> smem
    #pragma unroll
    for (int i = 0; i < 4; i++) {
        float4 v = *(const float4*)(Abase + (size_t)(aRow + 32 * i) * K_IN + aCol);
        *(float4*)&As[aRow + 32 * i][aCol] = v;
    }
    #pragma unroll
    for (int i = 0; i < 4; i++) {
        float4 v = *(const float4*)(W + (size_t)(bRow + 8 * i) * N_HID + colB0 + bCol);
        *(float4*)&Bs[bRow + 8 * i][bCol] = v;
    }
    __syncthreads();

    const int NT = K_IN / BK;  // 128
    for (int kt = 0; kt < NT; kt++) {
        // prefetch next K-tile into registers while computing current
        if (kt + 1 < NT) {
            const float* Ap = Abase + (size_t)(kt + 1) * BK;
            #pragma unroll
            for (int i = 0; i < 4; i++)
                pa[i] = *(const float4*)(Ap + (size_t)(aRow + 32 * i) * K_IN + aCol);
            const float* Wp = W + (size_t)(kt + 1) * BK * N_HID + colB0;
            #pragma unroll
            for (int i = 0; i < 4; i++)
                pb[i] = *(const float4*)(Wp + (size_t)(bRow + 8 * i) * N_HID + bCol);
        }

        #pragma unroll
        for (int k = 0; k < BK; k++) {
            float a[8], b[8];
            #pragma unroll
            for (int i = 0; i < 8; i++) a[i] = As[ty * 8 + i][k];
            *(float4*)&b[0] = *(float4*)&Bs[k][tx * 8];
            *(float4*)&b[4] = *(float4*)&Bs[k][tx * 8 + 4];
            #pragma unroll
            for (int i = 0; i < 8; i++)
                #pragma unroll
                for (int j = 0; j < 8; j++)
                    acc[i][j] += a[i] * b[j];
        }
        __syncthreads();

        if (kt + 1 < NT) {
            #pragma unroll
            for (int i = 0; i < 4; i++)
                *(float4*)&As[aRow + 32 * i][aCol] = pa[i];
            #pragma unroll
            for (int i = 0; i < 4; i++)
                *(float4*)&Bs[bRow + 8 * i][bCol] = pb[i];
            __syncthreads();
        }
    }

    // epilogue: + bias, relu, store h (vectorized)
    #pragma unroll
    for (int i = 0; i < 8; i++) {
        const int r = rowA0 + ty * 8 + i;
        float* out = g_h + (size_t)r * N_HID + colB0 + tx * 8;
        #pragma unroll
        for (int jj = 0; jj < 2; jj++) {
            float4 v;
            const int c = colB0 + tx * 8 + jj * 4;
            v.x = acc[i][jj * 4 + 0] + bias[c + 0];
            v.y = acc[i][jj * 4 + 1] + bias[c + 1];
            v.z = acc[i][jj * 4 + 2] + bias[c + 2];
            v.w = acc[i][jj * 4 + 3] + bias[c + 3];
            v.x = v.x > 0.f ? v.x : 0.f;
            v.y = v.y > 0.f ? v.y : 0.f;
            v.z = v.z > 0.f ? v.z : 0.f;
            v.w = v.w > 0.f ? v.w : 0.f;
            *(float4*)(out + jj * 4) = v;
        }
    }
}

// ---------------------------------------------------------------------------
// Kernel 2: logits = h @ w2 + b2; top-2 (stable, lower-index tie-break like
// lax.top_k); softmax over the 2 selected; scatter to dense output.
// One block = 64 tokens. h tile + w2^T staged in (dynamic) smem.
// ---------------------------------------------------------------------------
#define TB 64
#define HS 260   // padded row stride (floats): conflict-free, f4-aligned
#define LGS 68   // padded logits row stride

__global__ __launch_bounds__(256) void gate_kernel(
    const float* __restrict__ W2,   // [256,64]
    const float* __restrict__ B2,   // [64]
    float* __restrict__ out)        // [16384,64]
{
    extern __shared__ float sm2[];
    float* hs  = sm2;                 // [TB][HS]
    float* w2t = hs + TB * HS;        // [N_EXP][HS]  (w2 transposed)
    float* lg  = w2t + N_EXP * HS;    // [TB][LGS]
    float* sg1 = lg + TB * LGS;       // [TB]
    float* sg2 = sg1 + TB;            // [TB]
    int*   si1 = (int*)(sg2 + TB);    // [TB]
    int*   si2 = si1 + TB;            // [TB]

    const int tid = threadIdx.x;
    const int blk = blockIdx.x;
    const float* Hb = g_h + (size_t)blk * TB * N_HID;

    // stage h tile (64x256 f32, f4 loads)
    for (int idx = tid * 4; idx < TB * N_HID; idx += 256 * 4) {
        const int t = idx >> 8;
        const int k = idx & 255;
        float4 v = *(const float4*)(Hb + idx);
        *(float4*)&hs[t * HS + k] = v;
    }
    // stage w2 transposed: w2t[e][k] = W2[k*64+e]
    for (int idx = tid; idx < N_HID * N_EXP; idx += 256) {
        const int k = idx >> 6;
        const int e = idx & 63;
        w2t[e * HS + k] = W2[idx];
    }
    __syncthreads();

    // logits: thread = (expert e, token-group tg); 16 tokens/thread, 4 per pass
    const int e  = tid & 63;
    const int tg = tid >> 6;
    const float bias2 = B2[e];
    const float* wr = &w2t[e * HS];

    for (int q = 0; q < 4; q++) {
        const int tA = tg + 16 * q;   // tokens tA, tA+4, tA+8, tA+12
        float a0 = 0.f, a1 = 0.f, a2 = 0.f, a3 = 0.f;
        #pragma unroll 8
        for (int k = 0; k < N_HID; k += 4) {
            const float4 w4 = *(const float4*)&wr[k];
            const float4 h0 = *(const float4*)&hs[(tA + 0)  * HS + k];
            const float4 h1 = *(const float4*)&hs[(tA + 4)  * HS + k];
            const float4 h2 = *(const float4*)&hs[(tA + 8)  * HS + k];
            const float4 h3 = *(const float4*)&hs[(tA + 12) * HS + k];
            a0 += w4.x * h0.x + w4.y * h0.y + w4.z * h0.z + w4.w * h0.w;
            a1 += w4.x * h1.x + w4.y * h1.y + w4.z * h1.z + w4.w * h1.w;
            a2 += w4.x * h2.x + w4.y * h2.y + w4.z * h2.z + w4.w * h2.w;
            a3 += w4.x * h3.x + w4.y * h3.y + w4.z * h3.z + w4.w * h3.w;
        }
        lg[(tA + 0)  * LGS + e] = a0 + bias2;
        lg[(tA + 4)  * LGS + e] = a1 + bias2;
        lg[(tA + 8)  * LGS + e] = a2 + bias2;
        lg[(tA + 12) * LGS + e] = a3 + bias2;
    }
    __syncthreads();

    // top-2 per token, stable (strict >) to match lax.top_k tie-breaking
    if (tid < TB) {
        const int t = tid;
        float v1 = -3.4e38f, v2 = -3.4e38f;
        int i1 = 0, i2 = 0;
        #pragma unroll
        for (int ee = 0; ee < N_EXP; ee++) {
            const float v = lg[t * LGS + ee];
            if (v > v1) { v2 = v1; i2 = i1; v1 = v; i1 = ee; }
            else if (v > v2) { v2 = v; i2 = ee; }
        }
        // softmax over (v1, v2), v1 >= v2 (matches jax.nn.softmax with max-sub)
        const float ed  = expf(v2 - v1);
        const float inv = 1.f / (1.f + ed);
        sg1[t] = inv;
        sg2[t] = ed * inv;
        si1[t] = i1;
        si2[t] = i2;
    }
    __syncthreads();

    // scatter to dense output (coalesced)
    float* ob = out + (size_t)blk * TB * N_EXP;
    for (int idx = tid; idx < TB * N_EXP; idx += 256) {
        const int t  = idx >> 6;
        const int ee = idx & 63;
        float v = 0.f;
        if (ee == si1[t])      v = sg1[t];
        else if (ee == si2[t]) v = sg2[t];
        ob[idx] = v;
    }
}

// ---------------------------------------------------------------------------
extern "C" void kernel_launch(void* const* d_in, const int* in_sizes, int n_in,
                              void* d_out, int out_size) {
    const float* x  = (const float*)d_in[0];
    const float* w1 = (const float*)d_in[1];
    const float* b1 = (const float*)d_in[2];
    const float* w2 = (const float*)d_in[3];
    const float* b2 = (const float*)d_in[4];
    float* out = (float*)d_out;

    // dynamic smem for gate_kernel: hs + w2t + lg + gates/idx
    const int smem2 = (TB * HS + N_EXP * HS + TB * LGS + 4 * TB) * (int)sizeof(float);
    cudaFuncSetAttribute(gate_kernel,
                         cudaFuncAttributeMaxDynamicSharedMemorySize, smem2);

    dim3 g1(N_HID / BN, M_TOK / BM);   // (2, 128)
    gemm1_relu<<<g1, 256>>>(x, w1, b1);

    gate_kernel<<<M_TOK / TB, 256, smem2>>>(w2, b2, out);
}

// round 4
// speedup vs baseline: 1.9139x; 1.9139x over previous
#include <cuda_runtime.h>
#include <cstdint>

// SimpleGate: h = relu(x@w1+b1); logits = h@w2+b2; top-2 softmax scattered dense.
// R3: tcgen05 is unavailable (harness ptxas targets sm_100, not sm_100a).
// GEMM1 uses legacy mma.sync.m16n8k8 TF32 with 3-term split (fp32-class
// accuracy: a single top-2 selection flip fails the 1e-3 norm check).

#define M_TOK 16384
#define K_IN  4096
#define N_HID 256
#define N_EXP 64

// scratch (static: no allocations allowed)
__device__ float g_h[(size_t)M_TOK * N_HID];        // 16 MB
__device__ float g_w_hi[(size_t)K_IN * N_HID];      // 4 MB  tf32-truncated w1
__device__ float g_w_lo[(size_t)K_IN * N_HID];      // 4 MB  residual

__device__ __forceinline__ float tf32_hi(float x) {
    return __uint_as_float(__float_as_uint(x) & 0xFFFFE000u);
}

// ---------------------------------------------------------------------------
// pre-pass: elementwise split of w1 into hi/lo (same [K,N] layout)
// ---------------------------------------------------------------------------
__global__ __launch_bounds__(256) void wsplit(const float* __restrict__ w1) {
    const size_t i = ((size_t)blockIdx.x * 256 + threadIdx.x) * 4;
    float4 v = *(const float4*)(w1 + i);
    float4 hi, lo;
    hi.x = tf32_hi(v.x); lo.x = v.x - hi.x;
    hi.y = tf32_hi(v.y); lo.y = v.y - hi.y;
    hi.z = tf32_hi(v.z); lo.z = v.z - hi.z;
    hi.w = tf32_hi(v.w); lo.w = v.w - hi.w;
    *(float4*)(g_w_hi + i) = hi;
    *(float4*)(g_w_lo + i) = lo;
}

// ---------------------------------------------------------------------------
// GEMM1: h = relu(x @ w1 + b1), 3xTF32 mma.sync.
// Block 128x256 (full N), 256 threads = 8 warps (2m x 4n), warp tile 64x64.
// Double-buffered: W tiles via cp.async from pre-split g_w_hi/lo, x split
// on the fly in registers.
// ---------------------------------------------------------------------------
#define BM 128
#define BK 16
#define SA 20            // A smem row stride (floats): conflict-free
#define SB 264           // B smem row stride (floats): conflict-free, 16B-mult

// dynamic smem layout in floats
#define AHI_F  0                         // [2][128*SA]   = 5120
#define ALO_F  5120                      // [2][128*SA]   = 5120
#define BHI_F  10240                     // [2][16*SB]    = 8448
#define BLO_F  18688                     // [2][16*SB]    = 8448
#define BIAS_F 27136                     // [256]
#define SMEM_F (BIAS_F + 256)            // 27392 floats = 109568 B

#define A_STG (128 * SA)                 // 2560 floats per stage
#define B_STG (16 * SB)                  // 4224 floats per stage

__device__ __forceinline__ void mma_tf32(float c[4], const uint32_t a[4],
                                         const uint32_t b[2]) {
    asm volatile(
        "mma.sync.aligned.m16n8k8.row.col.f32.tf32.tf32.f32 "
        "{%0,%1,%2,%3}, {%4,%5,%6,%7}, {%8,%9}, {%0,%1,%2,%3};"
        : "+f"(c[0]), "+f"(c[1]), "+f"(c[2]), "+f"(c[3])
        : "r"(a[0]), "r"(a[1]), "r"(a[2]), "r"(a[3]), "r"(b[0]), "r"(b[1]));
}

__device__ __forceinline__ uint32_t smem_u32(const void* p) {
    uint32_t a;
    asm("{ .reg .u64 t; cvta.to.shared.u64 t, %1; cvt.u32.u64 %0, t; }"
        : "=r"(a) : "l"(p));
    return a;
}

__device__ __forceinline__ void cp16(uint32_t dst, const float* src) {
    asm volatile("cp.async.cg.shared.global [%0], [%1], 16;"
                 :: "r"(dst), "l"(src) : "memory");
}

__global__ __launch_bounds__(256, 1) void gemm1_mma(
    const float* __restrict__ x, const float* __restrict__ b1)
{
    extern __shared__ float sm[];
    const uint32_t smb = smem_u32(sm);
    const int tid = threadIdx.x;
    const int wid = tid >> 5;
    const int lid = tid & 31;
    const int row0 = blockIdx.x * BM;

    // bias stage
    sm[BIAS_F + tid] = b1[tid];

    // ---- producer mapping ----
    const int arow  = tid >> 1;            // 0..127
    const int ahalf = (tid & 1) * 8;       // 0 or 8
    const float* aptr = x + (size_t)(row0 + arow) * K_IN + ahalf;

    // B cp.async mapping: 2048 16B ops/stage, 8 per thread
    // id = tid + 256*u: tsel=id>>10, r=(id&1023)>>6, cq=id&63

    // ---- compute mapping ----
    const int wm = wid >> 2, wn = wid & 3;
    const int m0 = wm * 64, n0 = wn * 64;
    const int g = lid >> 2, t = lid & 3;

    float c[4][8][4];
    #pragma unroll
    for (int i = 0; i < 4; i++)
        #pragma unroll
        for (int j = 0; j < 8; j++)
            #pragma unroll
            for (int q = 0; q < 4; q++) c[i][j][q] = 0.f;

    const int NSTEP = K_IN / BK;  // 256

    // ---- prologue: fill stage 0 ----
    {
        const int k0 = 0;
        #pragma unroll
        for (int u = 0; u < 8; u++) {
            const int id = tid + 256 * u;
            const int tsel = id >> 10;
            const int r = (id & 1023) >> 6;
            const int cq = id & 63;
            const float* src = (tsel ? g_w_lo : g_w_hi)
                               + (size_t)(k0 + r) * N_HID + cq * 4;
            const uint32_t dst = smb + 4u * ((tsel ? BLO_F : BHI_F) + r * SB + cq * 4);
            cp16(dst, src);
        }
        asm volatile("cp.async.commit_group;");
        float4 ra0 = *(const float4*)(aptr + k0);
        float4 ra1 = *(const float4*)(aptr + k0 + 4);
        asm volatile("cp.async.wait_group 0;" ::: "memory");
        float* Ah = sm + AHI_F + arow * SA + ahalf;
        float* Al = sm + ALO_F + arow * SA + ahalf;
        float4 h0, l0, h1, l1;
        h0.x = tf32_hi(ra0.x); l0.x = ra0.x - h0.x;
        h0.y = tf32_hi(ra0.y); l0.y = ra0.y - h0.y;
        h0.z = tf32_hi(ra0.z); l0.z = ra0.z - h0.z;
        h0.w = tf32_hi(ra0.w); l0.w = ra0.w - h0.w;
        h1.x = tf32_hi(ra1.x); l1.x = ra1.x - h1.x;
        h1.y = tf32_hi(ra1.y); l1.y = ra1.y - h1.y;
        h1.z = tf32_hi(ra1.z); l1.z = ra1.z - h1.z;
        h1.w = tf32_hi(ra1.w); l1.w = ra1.w - h1.w;
        *(float4*)(Ah) = h0; *(float4*)(Ah + 4) = h1;
        *(float4*)(Al) = l0; *(float4*)(Al + 4) = l1;
    }
    __syncthreads();

    // ---- main loop ----
    for (int cs = 0; cs < NSTEP; cs++) {
        const int s = cs & 1, ns = s ^ 1;
        float4 ra0, ra1;
        const bool pf = (cs + 1 < NSTEP);

        if (pf) {
            const int k0 = (cs + 1) * BK;
            #pragma unroll
            for (int u = 0; u < 8; u++) {
                const int id = tid + 256 * u;
                const int tsel = id >> 10;
                const int r = (id & 1023) >> 6;
                const int cq = id & 63;
                const float* src = (tsel ? g_w_lo : g_w_hi)
                                   + (size_t)(k0 + r) * N_HID + cq * 4;
                const uint32_t dst = smb + 4u * ((tsel ? BLO_F : BHI_F)
                                                 + ns * B_STG + r * SB + cq * 4);
                cp16(dst, src);
            }
            asm volatile("cp.async.commit_group;");
            ra0 = *(const float4*)(aptr + k0);
            ra1 = *(const float4*)(aptr + k0 + 4);
        }

        // compute stage s
        {
            const uint32_t* Ah32 = (const uint32_t*)(sm + AHI_F + s * A_STG);
            const uint32_t* Al32 = (const uint32_t*)(sm + ALO_F + s * A_STG);
            const uint32_t* Bh32 = (const uint32_t*)(sm + BHI_F + s * B_STG);
            const uint32_t* Bl32 = (const uint32_t*)(sm + BLO_F + s * B_STG);

            #pragma unroll
            for (int kk = 0; kk < BK; kk += 8) {
                const int kr0 = kk + t, kr1 = kk + t + 4;
                uint32_t bh[8][2], bl[8][2], a[4][4];
                #pragma unroll
                for (int j = 0; j < 8; j++) {
                    const int col = n0 + 8 * j + g;
                    bh[j][0] = Bh32[kr0 * SB + col];
                    bh[j][1] = Bh32[kr1 * SB + col];
                    bl[j][0] = Bl32[kr0 * SB + col];
                    bl[j][1] = Bl32[kr1 * SB + col];
                }
                #pragma unroll
                for (int i = 0; i < 4; i++) {
                    const int row = m0 + g + 16 * i;
                    a[i][0] = Ah32[row * SA + kr0];
                    a[i][1] = Ah32[(row + 8) * SA + kr0];
                    a[i][2] = Ah32[row * SA + kr1];
                    a[i][3] = Ah32[(row + 8) * SA + kr1];
                }
                #pragma unroll
                for (int i = 0; i < 4; i++)
                    #pragma unroll
                    for (int j = 0; j < 8; j++) mma_tf32(c[i][j], a[i], bh[j]);
                #pragma unroll
                for (int i = 0; i < 4; i++)
                    #pragma unroll
                    for (int j = 0; j < 8; j++) mma_tf32(c[i][j], a[i], bl[j]);
                #pragma unroll
                for (int i = 0; i < 4; i++) {
                    const int row = m0 + g + 16 * i;
                    a[i][0] = Al32[row * SA + kr0];
                    a[i][1] = Al32[(row + 8) * SA + kr0];
                    a[i][2] = Al32[row * SA + kr1];
                    a[i][3] = Al32[(row + 8) * SA + kr1];
                }
                #pragma unroll
                for (int i = 0; i < 4; i++)
                    #pragma unroll
                    for (int j = 0; j < 8; j++) mma_tf32(c[i][j], a[i], bh[j]);
            }
        }

        if (pf) {
            asm volatile("cp.async.wait_group 0;" ::: "memory");
            float* Ah = sm + AHI_F + ns * A_STG + arow * SA + ahalf;
            float* Al = sm + ALO_F + ns * A_STG + arow * SA + ahalf;
            float4 h0, l0, h1, l1;
            h0.x = tf32_hi(ra0.x); l0.x = ra0.x - h0.x;
            h0.y = tf32_hi(ra0.y); l0.y = ra0.y - h0.y;
            h0.z = tf32_hi(ra0.z); l0.z = ra0.z - h0.z;
            h0.w = tf32_hi(ra0.w); l0.w = ra0.w - h0.w;
            h1.x = tf32_hi(ra1.x); l1.x = ra1.x - h1.x;
            h1.y = tf32_hi(ra1.y); l1.y = ra1.y - h1.y;
            h1.z = tf32_hi(ra1.z); l1.z = ra1.z - h1.z;
            h1.w = tf32_hi(ra1.w); l1.w = ra1.w - h1.w;
            *(float4*)(Ah) = h0; *(float4*)(Ah + 4) = h1;
            *(float4*)(Al) = l0; *(float4*)(Al + 4) = l1;
        }
        __syncthreads();
    }

    // ---- epilogue: bias + relu, write h ----
    const float* bias = sm + BIAS_F;
    #pragma unroll
    for (int i = 0; i < 4; i++) {
        const int row = row0 + m0 + g + 16 * i;
        #pragma unroll
        for (int j = 0; j < 8; j++) {
            const int col = n0 + 8 * j + 2 * t;
            const float bx = bias[col], by = bias[col + 1];
            float2 v0, v1;
            v0.x = fmaxf(c[i][j][0] + bx, 0.f);
            v0.y = fmaxf(c[i][j][1] + by, 0.f);
            v1.x = fmaxf(c[i][j][2] + bx, 0.f);
            v1.y = fmaxf(c[i][j][3] + by, 0.f);
            *(float2*)(g_h + (size_t)row * N_HID + col) = v0;
            *(float2*)(g_h + (size_t)(row + 8) * N_HID + col) = v1;
        }
    }
}

// ---------------------------------------------------------------------------
// Kernel 2 (unchanged, known good): logits = h @ w2 + b2; top-2 softmax
// scattered dense.
// ---------------------------------------------------------------------------
#define TB 64
#define HS 260
#define LGS 68

__global__ __launch_bounds__(256) void gate_kernel(
    const float* __restrict__ W2, const float* __restrict__ B2,
    float* __restrict__ out)
{
    extern __shared__ float sm2[];
    float* hs  = sm2;
    float* w2t = hs + TB * HS;
    float* lg  = w2t + N_EXP * HS;
    float* sg1 = lg + TB * LGS;
    float* sg2 = sg1 + TB;
    int*   si1 = (int*)(sg2 + TB);
    int*   si2 = si1 + TB;

    const int tid = threadIdx.x;
    const int blk = blockIdx.x;
    const float* Hb = g_h + (size_t)blk * TB * N_HID;

    for (int idx = tid * 4; idx < TB * N_HID; idx += 256 * 4) {
        const int t = idx >> 8;
        const int k = idx & 255;
        float4 v = *(const float4*)(Hb + idx);
        *(float4*)&hs[t * HS + k] = v;
    }
    for (int idx = tid; idx < N_HID * N_EXP; idx += 256) {
        const int k = idx >> 6;
        const int e = idx & 63;
        w2t[e * HS + k] = W2[idx];
    }
    __syncthreads();

    const int e  = tid & 63;
    const int tg = tid >> 6;
    const float bias2 = B2[e];
    const float* wr = &w2t[e * HS];

    for (int q = 0; q < 4; q++) {
        const int tA = tg + 16 * q;
        float a0 = 0.f, a1 = 0.f, a2 = 0.f, a3 = 0.f;
        #pragma unroll 8
        for (int k = 0; k < N_HID; k += 4) {
            const float4 w4 = *(const float4*)&wr[k];
            const float4 h0 = *(const float4*)&hs[(tA + 0)  * HS + k];
            const float4 h1 = *(const float4*)&hs[(tA + 4)  * HS + k];
            const float4 h2 = *(const float4*)&hs[(tA + 8)  * HS + k];
            const float4 h3 = *(const float4*)&hs[(tA + 12) * HS + k];
            a0 += w4.x * h0.x + w4.y * h0.y + w4.z * h0.z + w4.w * h0.w;
            a1 += w4.x * h1.x + w4.y * h1.y + w4.z * h1.z + w4.w * h1.w;
            a2 += w4.x * h2.x + w4.y * h2.y + w4.z * h2.z + w4.w * h2.w;
            a3 += w4.x * h3.x + w4.y * h3.y + w4.z * h3.z + w4.w * h3.w;
        }
        lg[(tA + 0)  * LGS + e] = a0 + bias2;
        lg[(tA + 4)  * LGS + e] = a1 + bias2;
        lg[(tA + 8)  * LGS + e] = a2 + bias2;
        lg[(tA + 12) * LGS + e] = a3 + bias2;
    }
    __syncthreads();

    if (tid < TB) {
        const int t = tid;
        float v1 = -3.4e38f, v2 = -3.4e38f;
        int i1 = 0, i2 = 0;
        #pragma unroll
        for (int ee = 0; ee < N_EXP; ee++) {
            const float v = lg[t * LGS + ee];
            if (v > v1) { v2 = v1; i2 = i1; v1 = v; i1 = ee; }
            else if (v > v2) { v2 = v; i2 = ee; }
        }
        const float ed  = expf(v2 - v1);
        const float inv = 1.f / (1.f + ed);
        sg1[t] = inv;
        sg2[t] = ed * inv;
        si1[t] = i1;
        si2[t] = i2;
    }
    __syncthreads();

    float* ob = out + (size_t)blk * TB * N_EXP;
    for (int idx = tid; idx < TB * N_EXP; idx += 256) {
        const int t  = idx >> 6;
        const int ee = idx & 63;
        float v = 0.f;
        if (ee == si1[t])      v = sg1[t];
        else if (ee == si2[t]) v = sg2[t];
        ob[idx] = v;
    }
}

// ---------------------------------------------------------------------------
extern "C" void kernel_launch(void* const* d_in, const int* in_sizes, int n_in,
                              void* d_out, int out_size) {
    const float* x  = (const float*)d_in[0];
    const float* w1 = (const float*)d_in[1];
    const float* b1 = (const float*)d_in[2];
    const float* w2 = (const float*)d_in[3];
    const float* b2 = (const float*)d_in[4];
    float* out = (float*)d_out;

    const int smem1 = SMEM_F * (int)sizeof(float);
    const int smem2 = (TB * HS + N_EXP * HS + TB * LGS + 4 * TB) * (int)sizeof(float);
    cudaFuncSetAttribute(gemm1_mma, cudaFuncAttributeMaxDynamicSharedMemorySize, smem1);
    cudaFuncSetAttribute(gate_kernel, cudaFuncAttributeMaxDynamicSharedMemorySize, smem2);

    wsplit<<<(K_IN * N_HID) / (256 * 4), 256>>>(w1);
    gemm1_mma<<<M_TOK / BM, 256, smem1>>>(x, b1);
    gate_kernel<<<M_TOK / TB, 256, smem2>>>(w2, b2, out);
}